// round 3
// baseline (speedup 1.0000x reference)
#include <cuda_runtime.h>
#include <cuda_bf16.h>

#define HW_  4096
#define C_   256
#define B_   4

// Scratch (allocation-free rule: __device__ globals)
__device__ float g_x1[B_ * C_ * HW_];            // relu(conv(ref,w1))  [b][c][pos]
__device__ float g_v [B_ * C_ * HW_];            // relu(conv(ref,w2))  [b][c][pos]
__device__ float g_S [(size_t)B_ * HW_ * HW_];   // raw scores (symmetric per batch)
__device__ float g_mx [B_ * HW_];                // colmax  (== rowmax by symmetry)
__device__ float g_rcp[B_ * HW_];                // 1 / colsum per (b, m)

// ---------------------------------------------------------------------------
// FMA-pipe exp (x <= 0 expected). 2^f Taylor(6) after range reduction.
// ---------------------------------------------------------------------------
__device__ __forceinline__ float fast_exp(float x) {
    x = fmaxf(x, -87.0f);
    float y  = x * 1.4426950408889634f;     // log2(e)
    float fl = floorf(y);
    float f  = y - fl;                       // [0,1)
    float t  = f * 0.6931471805599453f;      // f*ln2
    float p = 1.3888889e-3f;                 // 1/720
    p = fmaf(p, t, 8.3333333e-3f);           // 1/120
    p = fmaf(p, t, 4.1666667e-2f);           // 1/24
    p = fmaf(p, t, 1.6666667e-1f);           // 1/6
    p = fmaf(p, t, 0.5f);
    p = fmaf(p, t, 1.0f);
    p = fmaf(p, t, 1.0f);
    int e = (int)fl;
    return __int_as_float((e + 127) << 23) * p;
}

// ---------------------------------------------------------------------------
// Conv 3x3 SAME + ReLU as implicit GEMM: M=256 (co), N=16384 (b,pos), K=2304
// ---------------------------------------------------------------------------
__global__ __launch_bounds__(256) void conv_relu_kernel(
    const float* __restrict__ in, const float* __restrict__ w, int which_out)
{
    __shared__ float As[8][128];   // [k][co]
    __shared__ float Bs[8][128];   // [k][n]
    float* __restrict__ out = which_out ? g_v : g_x1;

    const int t    = threadIdx.x;
    const int m0   = blockIdx.y * 128;       // co base
    const int n0   = blockIdx.x * 128;       // global spatial base (b*4096 + pos)
    const int b    = n0 >> 12;
    const int pos0 = n0 & 4095;

    const int tm = (t >> 4) * 8;
    const int tn = (t & 15) * 8;
    const int a_row  = t >> 1;
    const int a_koff = (t & 1) * 4;

    float acc[8][8] = {};

    for (int k0 = 0; k0 < 2304; k0 += 8) {
        float4 av = *(const float4*)(w + (m0 + a_row) * 2304 + k0 + a_koff);
        As[a_koff + 0][a_row] = av.x;
        As[a_koff + 1][a_row] = av.y;
        As[a_koff + 2][a_row] = av.z;
        As[a_koff + 3][a_row] = av.w;
        #pragma unroll
        for (int i = 0; i < 4; i++) {
            int idx = t + i * 256;
            int kk  = idx >> 7;
            int col = idx & 127;
            int kg  = k0 + kk;
            int ci  = kg / 9;
            int t9  = kg - ci * 9;
            int dy  = t9 / 3 - 1;
            int dx  = t9 - (t9 / 3) * 3 - 1;
            int pos = pos0 + col;
            int y   = pos >> 6, x = pos & 63;
            int yy  = y + dy,  xx = x + dx;
            float val = 0.0f;
            if ((unsigned)yy < 64u && (unsigned)xx < 64u)
                val = in[(((b << 8) + ci) << 12) + (yy << 6) + xx];
            Bs[kk][col] = val;
        }
        __syncthreads();
        #pragma unroll
        for (int k = 0; k < 8; k++) {
            float4 a0 = *(const float4*)&As[k][tm];
            float4 a1 = *(const float4*)&As[k][tm + 4];
            float4 b0 = *(const float4*)&Bs[k][tn];
            float4 b1 = *(const float4*)&Bs[k][tn + 4];
            float ar[8] = {a0.x, a0.y, a0.z, a0.w, a1.x, a1.y, a1.z, a1.w};
            float br[8] = {b0.x, b0.y, b0.z, b0.w, b1.x, b1.y, b1.z, b1.w};
            #pragma unroll
            for (int i = 0; i < 8; i++)
                #pragma unroll
                for (int j = 0; j < 8; j++)
                    acc[i][j] = fmaf(ar[i], br[j], acc[i][j]);
        }
        __syncthreads();
    }
    #pragma unroll
    for (int i = 0; i < 8; i++) {
        int m = m0 + tm + i;
        float* op = out + (((b << 8) + m) << 12) + pos0 + tn;
        #pragma unroll
        for (int j = 0; j < 8; j++)
            op[j] = fmaxf(acc[i][j], 0.0f);
    }
}

// ---------------------------------------------------------------------------
// S[b][n][m] = sum_c x1[b][c][n] * x1[b][c][m]   (M=N=4096, K=256)
// ---------------------------------------------------------------------------
__global__ __launch_bounds__(256) void scores_kernel()
{
    __shared__ float As[8][128];   // [k][n]
    __shared__ float Bs[8][128];   // [k][m]
    const int t     = threadIdx.x;
    const int b     = blockIdx.z;
    const int nbase = blockIdx.y * 128;
    const int mbase = blockIdx.x * 128;
    const float* __restrict__ Xb = g_x1 + b * C_ * HW_;

    const int tm = (t >> 4) * 8;
    const int tn = (t & 15) * 8;
    float acc[8][8] = {};

    for (int k0 = 0; k0 < 256; k0 += 8) {
        #pragma unroll
        for (int i = 0; i < 4; i++) {
            int idx = t + i * 256;
            int kk  = idx >> 7;
            int col = idx & 127;
            As[kk][col] = Xb[(k0 + kk) * HW_ + nbase + col];
            Bs[kk][col] = Xb[(k0 + kk) * HW_ + mbase + col];
        }
        __syncthreads();
        #pragma unroll
        for (int k = 0; k < 8; k++) {
            float4 a0 = *(const float4*)&As[k][tm];
            float4 a1 = *(const float4*)&As[k][tm + 4];
            float4 b0 = *(const float4*)&Bs[k][tn];
            float4 b1 = *(const float4*)&Bs[k][tn + 4];
            float ar[8] = {a0.x, a0.y, a0.z, a0.w, a1.x, a1.y, a1.z, a1.w};
            float br[8] = {b0.x, b0.y, b0.z, b0.w, b1.x, b1.y, b1.z, b1.w};
            #pragma unroll
            for (int i = 0; i < 8; i++)
                #pragma unroll
                for (int j = 0; j < 8; j++)
                    acc[i][j] = fmaf(ar[i], br[j], acc[i][j]);
        }
        __syncthreads();
    }
    float* Sp = g_S + (size_t)b * HW_ * HW_;
    #pragma unroll
    for (int i = 0; i < 8; i++) {
        float* row = Sp + (size_t)(nbase + tm + i) * HW_ + mbase + tn;
        #pragma unroll
        for (int j = 0; j < 8; j++) row[j] = acc[i][j];
    }
}

// ---------------------------------------------------------------------------
// Softmax stats via symmetry: column m stats over n == row m stats.
// One block per row; contiguous float4 reads; single pass (values kept in regs).
// ---------------------------------------------------------------------------
__global__ __launch_bounds__(256) void rowstats_kernel()
{
    __shared__ float red[256];
    const int b = blockIdx.y;
    const int m = blockIdx.x;
    const int t = threadIdx.x;
    const float* __restrict__ row = g_S + ((size_t)b * HW_ + m) * HW_;

    float4 v[4];
    #pragma unroll
    for (int i = 0; i < 4; i++)
        v[i] = *(const float4*)(row + i * 1024 + t * 4);

    float mx = -1e30f;
    #pragma unroll
    for (int i = 0; i < 4; i++) {
        mx = fmaxf(mx, fmaxf(fmaxf(v[i].x, v[i].y), fmaxf(v[i].z, v[i].w)));
    }
    red[t] = mx;
    __syncthreads();
    #pragma unroll
    for (int s = 128; s >= 32; s >>= 1) {
        if (t < s) red[t] = fmaxf(red[t], red[t + s]);
        __syncthreads();
    }
    if (t < 32) {
        float r = red[t];
        #pragma unroll
        for (int o = 16; o > 0; o >>= 1)
            r = fmaxf(r, __shfl_xor_sync(0xffffffffu, r, o));
        red[0] = r;
    }
    __syncthreads();
    mx = red[0];
    __syncthreads();

    float sum = 0.0f;
    #pragma unroll
    for (int i = 0; i < 4; i++) {
        sum += fast_exp(v[i].x - mx) + fast_exp(v[i].y - mx)
             + fast_exp(v[i].z - mx) + fast_exp(v[i].w - mx);
    }
    red[t] = sum;
    __syncthreads();
    #pragma unroll
    for (int s = 128; s >= 32; s >>= 1) {
        if (t < s) red[t] += red[t + s];
        __syncthreads();
    }
    if (t < 32) {
        float r = red[t];
        #pragma unroll
        for (int o = 16; o > 0; o >>= 1)
            r += __shfl_xor_sync(0xffffffffu, r, o);
        if (t == 0) {
            g_mx [b * HW_ + m] = mx;
            g_rcp[b * HW_ + m] = 1.0f / r;
        }
    }
}

// ---------------------------------------------------------------------------
// A = v @ exp(S - mx[m]),  out = gamma * A * rcp[m] + ref
// M=256 (c), N=4096 (m), K=4096 (n), per batch. exp fused into B-tile load.
// ---------------------------------------------------------------------------
__global__ __launch_bounds__(256) void av_kernel(
    const float* __restrict__ ref, const float* __restrict__ gamma_p,
    float* __restrict__ out)
{
    __shared__ float As[8][128];   // [k][c]
    __shared__ float Bs[8][128];   // [k][m]
    __shared__ float s_mx[128];
    const int t  = threadIdx.x;
    const int b  = blockIdx.z;
    const int c0 = blockIdx.y * 128;
    const int m0 = blockIdx.x * 128;
    const float* __restrict__ Vb = g_v + b * C_ * HW_;
    const float* __restrict__ Sb = g_S + (size_t)b * HW_ * HW_;

    if (t < 128) s_mx[t] = g_mx[b * HW_ + m0 + t];
    __syncthreads();

    const int tm = (t >> 4) * 8;
    const int tn = (t & 15) * 8;
    const int a_row  = t >> 1;
    const int a_koff = (t & 1) * 4;
    float acc[8][8] = {};

    for (int k0 = 0; k0 < HW_; k0 += 8) {
        float4 av = *(const float4*)(Vb + (c0 + a_row) * HW_ + k0 + a_koff);
        As[a_koff + 0][a_row] = av.x;
        As[a_koff + 1][a_row] = av.y;
        As[a_koff + 2][a_row] = av.z;
        As[a_koff + 3][a_row] = av.w;
        #pragma unroll
        for (int i = 0; i < 4; i++) {
            int idx = t + i * 256;
            int kk  = idx >> 7;
            int col = idx & 127;
            float s = Sb[(size_t)(k0 + kk) * HW_ + m0 + col];
            Bs[kk][col] = fast_exp(s - s_mx[col]);
        }
        __syncthreads();
        #pragma unroll
        for (int k = 0; k < 8; k++) {
            float4 a0 = *(const float4*)&As[k][tm];
            float4 a1 = *(const float4*)&As[k][tm + 4];
            float4 b0 = *(const float4*)&Bs[k][tn];
            float4 b1 = *(const float4*)&Bs[k][tn + 4];
            float ar[8] = {a0.x, a0.y, a0.z, a0.w, a1.x, a1.y, a1.z, a1.w};
            float br[8] = {b0.x, b0.y, b0.z, b0.w, b1.x, b1.y, b1.z, b1.w};
            #pragma unroll
            for (int i = 0; i < 8; i++)
                #pragma unroll
                for (int j = 0; j < 8; j++)
                    acc[i][j] = fmaf(ar[i], br[j], acc[i][j]);
        }
        __syncthreads();
    }

    const float g = *gamma_p;
    float rc[8];
    #pragma unroll
    for (int j = 0; j < 8; j++) rc[j] = g * g_rcp[b * HW_ + m0 + tn + j];

    #pragma unroll
    for (int i = 0; i < 8; i++) {
        int c = c0 + tm + i;
        size_t base = (((size_t)b * C_ + c) * HW_) + m0 + tn;
        const float* rp = ref + base;
        float* op = out + base;
        #pragma unroll
        for (int j = 0; j < 8; j++)
            op[j] = fmaf(acc[i][j], rc[j], rp[j]);
    }
}

// ---------------------------------------------------------------------------
extern "C" void kernel_launch(void* const* d_in, const int* in_sizes, int n_in,
                              void* d_out, int out_size)
{
    // metadata order: inputs, ref, w1, w2, gamma
    // 'inputs' is dead in the reference (its conv result is overwritten) -> skip it.
    const float* ref   = (const float*)d_in[1];
    const float* w1    = (const float*)d_in[2];
    const float* w2    = (const float*)d_in[3];
    const float* gamma = (const float*)d_in[4];
    float* out = (float*)d_out;

    conv_relu_kernel<<<dim3(128, 2), 256>>>(ref, w1, 0);
    conv_relu_kernel<<<dim3(128, 2), 256>>>(ref, w2, 1);
    scores_kernel<<<dim3(32, 32, 4), 256>>>();
    rowstats_kernel<<<dim3(4096, 4), 256>>>();
    av_kernel<<<dim3(32, 2, 4), 256>>>(ref, gamma, out);
}